// round 4
// baseline (speedup 1.0000x reference)
#include <cuda_runtime.h>
#include <cuda_bf16.h>
#include <cstdint>

#define N_NODES 50000
#define N_EDGES 800000
#define F 128

// ---- device scratch (no allocs allowed) ----
__device__ float g_h[N_NODES * F];        // h = feat @ Wp^T + bp
__device__ float g_wsum[N_NODES];
__device__ int   g_cnt[N_NODES];
__device__ int   g_rowptr[N_NODES + 1];
__device__ int   g_cursor[N_NODES];
__device__ int   g_ssrc[N_EDGES];         // src sorted by dst
__device__ float g_sm[N_EDGES];           // m  sorted by dst
__device__ __nv_bfloat16 g_wh[2][F * F];  // [mat][n*F+k] hi split of W (0=Wp,1=Ws)
__device__ __nv_bfloat16 g_wl[2][F * F];  // lo split

// ======================= small kernels (CSR build) =======================
__global__ void k_init() {
    int i = blockIdx.x * blockDim.x + threadIdx.x;
    if (i < N_NODES) { g_wsum[i] = 0.f; g_cnt[i] = 0; }
}

__global__ void k_count(const float* __restrict__ efeat, const int* __restrict__ dst) {
    int e = blockIdx.x * blockDim.x + threadIdx.x;
    if (e < N_EDGES) {
        int d = dst[e];
        atomicAdd(&g_wsum[d], efeat[e]);
        atomicAdd(&g_cnt[d], 1);
    }
}

__global__ void k_scan() {
    __shared__ int wsums[32];
    __shared__ int s_total;
    int t = threadIdx.x, lane = t & 31, wid = t >> 5;
    int carry = 0;
    for (int base = 0; base < N_NODES; base += 4096) {
        int i0 = base + t * 4;
        int x0 = 0, x1 = 0, x2 = 0, x3 = 0;
        if (i0 + 3 < N_NODES) {
            int4 v = *(const int4*)&g_cnt[i0];
            x0 = v.x; x1 = v.y; x2 = v.z; x3 = v.w;
        } else {
            if (i0 + 0 < N_NODES) x0 = g_cnt[i0 + 0];
            if (i0 + 1 < N_NODES) x1 = g_cnt[i0 + 1];
            if (i0 + 2 < N_NODES) x2 = g_cnt[i0 + 2];
            if (i0 + 3 < N_NODES) x3 = g_cnt[i0 + 3];
        }
        int s1 = x0, s2 = s1 + x1, s3 = s2 + x2, s4 = s3 + x3;
        int v = s4;
        #pragma unroll
        for (int off = 1; off < 32; off <<= 1) {
            int u = __shfl_up_sync(0xffffffffu, v, off);
            if (lane >= off) v += u;
        }
        int warp_excl = v - s4;
        if (lane == 31) wsums[wid] = v;
        __syncthreads();
        if (t < 32) {
            int wv = wsums[t];
            int vv = wv;
            #pragma unroll
            for (int off = 1; off < 32; off <<= 1) {
                int u = __shfl_up_sync(0xffffffffu, vv, off);
                if (t >= off) vv += u;
            }
            wsums[t] = vv - wv;
            if (t == 31) s_total = vv;
        }
        __syncthreads();
        int bofs = carry + wsums[wid] + warp_excl;
        if (i0 + 0 < N_NODES) { g_rowptr[i0 + 0] = bofs;      g_cursor[i0 + 0] = bofs;      }
        if (i0 + 1 < N_NODES) { g_rowptr[i0 + 1] = bofs + s1; g_cursor[i0 + 1] = bofs + s1; }
        if (i0 + 2 < N_NODES) { g_rowptr[i0 + 2] = bofs + s2; g_cursor[i0 + 2] = bofs + s2; }
        if (i0 + 3 < N_NODES) { g_rowptr[i0 + 3] = bofs + s3; g_cursor[i0 + 3] = bofs + s3; }
        carry += s_total;
        __syncthreads();
    }
    if (t == 0) g_rowptr[N_NODES] = carry;
}

__global__ void k_scatter(const float* __restrict__ efeat, const int* __restrict__ src,
                          const int* __restrict__ dst) {
    int e = blockIdx.x * blockDim.x + threadIdx.x;
    if (e < N_EDGES) {
        int d = dst[e];
        float w = efeat[e];
        float m = expf(-w / g_wsum[d]);
        int pos = atomicAdd(&g_cursor[d], 1);
        g_ssrc[pos] = src[e];
        g_sm[pos] = m;
    }
}

// ---- split W matrices into hi/lo bf16 (once) ----
__global__ void k_wsplit(const float* __restrict__ Wp, const float* __restrict__ Ws) {
    int i = blockIdx.x * blockDim.x + threadIdx.x;
    if (i < F * F) {
        float w = Wp[i];
        __nv_bfloat16 h = __float2bfloat16(w);
        g_wh[0][i] = h;
        g_wl[0][i] = __float2bfloat16(w - __bfloat162float(h));
        w = Ws[i];
        h = __float2bfloat16(w);
        g_wh[1][i] = h;
        g_wl[1][i] = __float2bfloat16(w - __bfloat162float(h));
    }
}

// ======================= HMMA dual GEMM (bf16x3 split) =======================
// D0 = feat@Wp^T + bp -> g_h ; D1 = feat@Ws^T + bs -> out
// split: x = hi + lo ; D = Ahi*Bhi + Ahi*Blo + Alo*Bhi (fp32 accum via mma.sync)

#define STRIDE 136                         // bf16 elems per smem row (padded)
#define SM_A_HI 0
#define SM_A_LO (128 * STRIDE)             // elem offsets
#define SM_W_HI (2 * 128 * STRIDE)
#define SM_W_LO (3 * 128 * STRIDE)
#define SM_GEMM_BYTES (4 * 128 * STRIDE * 2)   // 139264

__device__ __forceinline__ uint32_t smem_u32(const void* p) {
    uint32_t a;
    asm("{ .reg .u64 t; cvta.to.shared.u64 t, %1; cvt.u32.u64 %0, t; }" : "=r"(a) : "l"(p));
    return a;
}
__device__ __forceinline__ void ldsm4(uint32_t& r0, uint32_t& r1, uint32_t& r2, uint32_t& r3,
                                      uint32_t addr) {
    asm volatile("ldmatrix.sync.aligned.m8n8.x4.shared.b16 {%0,%1,%2,%3},[%4];"
                 : "=r"(r0), "=r"(r1), "=r"(r2), "=r"(r3) : "r"(addr));
}
__device__ __forceinline__ void mma16816(float* d, const uint32_t* a, uint32_t b0, uint32_t b1) {
    asm volatile(
        "mma.sync.aligned.m16n8k16.row.col.f32.bf16.bf16.f32 "
        "{%0,%1,%2,%3},{%4,%5,%6,%7},{%8,%9},{%0,%1,%2,%3};"
        : "+f"(d[0]), "+f"(d[1]), "+f"(d[2]), "+f"(d[3])
        : "r"(a[0]), "r"(a[1]), "r"(a[2]), "r"(a[3]), "r"(b0), "r"(b1));
}
__device__ __forceinline__ unsigned pack2(__nv_bfloat16 a, __nv_bfloat16 b) {
    return (unsigned)__bfloat16_as_ushort(a) | ((unsigned)__bfloat16_as_ushort(b) << 16);
}

__global__ __launch_bounds__(256, 1)
void k_gemm_mma(const float* __restrict__ feat,
                const float* __restrict__ bp, const float* __restrict__ bs,
                float* __restrict__ out) {
    extern __shared__ __nv_bfloat16 sm[];
    int tid = threadIdx.x, w = tid >> 5, lane = tid & 31;
    int m0 = blockIdx.x * 128;
    int rows_valid = N_NODES - m0; if (rows_valid > 128) rows_valid = 128;

    // ---- convert A tile (128x128 f32 -> hi/lo bf16, padded smem) ----
    for (int i = tid; i < 4096; i += 256) {          // 4096 float4s
        int r = i >> 5, c4 = (i & 31) << 2;
        float4 v = make_float4(0.f, 0.f, 0.f, 0.f);
        if (r < rows_valid) v = *(const float4*)&feat[(long)(m0 + r) * F + c4];
        __nv_bfloat16 h0 = __float2bfloat16(v.x), h1 = __float2bfloat16(v.y);
        __nv_bfloat16 h2 = __float2bfloat16(v.z), h3 = __float2bfloat16(v.w);
        __nv_bfloat16 l0 = __float2bfloat16(v.x - __bfloat162float(h0));
        __nv_bfloat16 l1 = __float2bfloat16(v.y - __bfloat162float(h1));
        __nv_bfloat16 l2 = __float2bfloat16(v.z - __bfloat162float(h2));
        __nv_bfloat16 l3 = __float2bfloat16(v.w - __bfloat162float(h3));
        int o = r * STRIDE + c4;
        *(uint2*)&sm[SM_A_HI + o] = make_uint2(pack2(h0, h1), pack2(h2, h3));
        *(uint2*)&sm[SM_A_LO + o] = make_uint2(pack2(l0, l1), pack2(l2, l3));
    }

    uint32_t sb = smem_u32(sm);
    // ldmatrix source addresses (byte offsets added per k-step)
    uint32_t aRow = (uint32_t)(w * 16 + (lane & 15));
    uint32_t aColB = (uint32_t)((lane >> 4) << 4);                 // +8 elems -> 16B
    uint32_t aHiAddr = sb + SM_A_HI * 2 + aRow * (STRIDE * 2) + aColB;
    uint32_t aLoAddr = sb + SM_A_LO * 2 + aRow * (STRIDE * 2) + aColB;
    uint32_t bRowIn16 = (uint32_t)((lane & 7) + ((lane >> 4) << 3));
    uint32_t bColB = (uint32_t)(((lane >> 3) & 1) << 4);
    uint32_t bHiBase = sb + SM_W_HI * 2 + bRowIn16 * (STRIDE * 2) + bColB;
    uint32_t bLoBase = sb + SM_W_LO * 2 + bRowIn16 * (STRIDE * 2) + bColB;

    #pragma unroll
    for (int mat = 0; mat < 2; ++mat) {
        // ---- load pre-split W tile into smem ----
        __syncthreads();     // mat1: wait until all warps done reading previous W
        for (int i = tid; i < 4096; i += 256) {
            int r = i >> 5, c4 = (i & 31) << 2;
            int o = r * STRIDE + c4;
            *(uint2*)&sm[SM_W_HI + o] = *(const uint2*)&g_wh[mat][r * F + c4];
            *(uint2*)&sm[SM_W_LO + o] = *(const uint2*)&g_wl[mat][r * F + c4];
        }
        __syncthreads();

        float d[16][4];
        #pragma unroll
        for (int nt = 0; nt < 16; ++nt)
            #pragma unroll
            for (int j = 0; j < 4; ++j) d[nt][j] = 0.f;

        #pragma unroll
        for (int k = 0; k < 8; ++k) {
            uint32_t kOffB = (uint32_t)(k * 32);    // 16 elems = 32B
            uint32_t ahi[4], alo[4];
            ldsm4(ahi[0], ahi[1], ahi[2], ahi[3], aHiAddr + kOffB);
            ldsm4(alo[0], alo[1], alo[2], alo[3], aLoAddr + kOffB);
            #pragma unroll
            for (int bt = 0; bt < 8; ++bt) {        // 16 n-rows per iteration
                uint32_t nOffB = (uint32_t)(bt * 16 * STRIDE * 2);
                uint32_t bh[4], bl[4];
                ldsm4(bh[0], bh[1], bh[2], bh[3], bHiBase + nOffB + kOffB);
                ldsm4(bl[0], bl[1], bl[2], bl[3], bLoBase + nOffB + kOffB);
                mma16816(d[bt * 2],     ahi, bh[0], bh[1]);
                mma16816(d[bt * 2 + 1], ahi, bh[2], bh[3]);
                mma16816(d[bt * 2],     ahi, bl[0], bl[1]);
                mma16816(d[bt * 2 + 1], ahi, bl[2], bl[3]);
                mma16816(d[bt * 2],     alo, bh[0], bh[1]);
                mma16816(d[bt * 2 + 1], alo, bh[2], bh[3]);
            }
        }

        // ---- epilogue: registers -> gmem with bias ----
        const float* bias = mat ? bs : bp;
        float* dstp = mat ? out : g_h;
        int r0 = m0 + w * 16 + (lane >> 2);
        #pragma unroll
        for (int nt = 0; nt < 16; ++nt) {
            int c = nt * 8 + (lane & 3) * 2;
            float b0 = __ldg(&bias[c]), b1 = __ldg(&bias[c + 1]);
            if (r0 < N_NODES) {
                float2 v = make_float2(d[nt][0] + b0, d[nt][1] + b1);
                *(float2*)&dstp[(long)r0 * F + c] = v;
            }
            if (r0 + 8 < N_NODES) {
                float2 v = make_float2(d[nt][2] + b0, d[nt][3] + b1);
                *(float2*)&dstp[(long)(r0 + 8) * F + c] = v;
            }
        }
    }
}

// ======================= warp-per-node CSR aggregation =======================
__global__ void k_agg(float* __restrict__ out) {
    int node = (blockIdx.x * blockDim.x + threadIdx.x) >> 5;
    int lane = threadIdx.x & 31;
    if (node >= N_NODES) return;
    int beg = g_rowptr[node], end = g_rowptr[node + 1];

    float4 acc = make_float4(0.f, 0.f, 0.f, 0.f);
    for (int e0 = beg; e0 < end; e0 += 32) {
        int i = e0 + lane;
        int s = 0; float mv = 0.f;
        if (i < end) { s = g_ssrc[i]; mv = g_sm[i]; }
        int cnt = min(32, end - e0);
        for (int j = 0; j < cnt; ++j) {
            int ss = __shfl_sync(0xffffffffu, s, j);
            float mm = __shfl_sync(0xffffffffu, mv, j);
            float4 hv = *(const float4*)&g_h[(long)ss * F + lane * 4];
            acc.x += mm * hv.x;
            acc.y += mm * hv.y;
            acc.z += mm * hv.z;
            acc.w += mm * hv.w;
        }
    }
    int deg = end - beg;
    float inv = 1.0f / (float)(deg > 1 ? deg : 1);
    float4* po = (float4*)&out[(long)node * F + lane * 4];
    float4 o = *po;
    o.x += acc.x * inv;
    o.y += acc.y * inv;
    o.z += acc.z * inv;
    o.w += acc.w * inv;
    *po = o;
}

extern "C" void kernel_launch(void* const* d_in, const int* in_sizes, int n_in,
                              void* d_out, int out_size) {
    const float* feat  = (const float*)d_in[0];
    const float* efeat = (const float*)d_in[1];
    const int*   src   = (const int*)d_in[2];
    const int*   dst   = (const int*)d_in[3];
    const float* Wp    = (const float*)d_in[4];
    const float* bp    = (const float*)d_in[5];
    const float* Ws    = (const float*)d_in[6];
    const float* bs    = (const float*)d_in[7];
    float* out = (float*)d_out;

    cudaFuncSetAttribute(k_gemm_mma, cudaFuncAttributeMaxDynamicSharedMemorySize, SM_GEMM_BYTES);

    k_wsplit<<<(F * F + 255) / 256, 256>>>(Wp, Ws);
    k_init<<<(N_NODES + 255) / 256, 256>>>();
    k_count<<<(N_EDGES + 255) / 256, 256>>>(efeat, dst);
    k_scan<<<1, 1024>>>();
    k_scatter<<<(N_EDGES + 255) / 256, 256>>>(efeat, src, dst);
    k_gemm_mma<<<(N_NODES + 127) / 128, 256, SM_GEMM_BYTES>>>(feat, bp, bs, out);
    k_agg<<<(N_NODES * 32 + 255) / 256, 256>>>(out);
}

// round 5
// speedup vs baseline: 1.9483x; 1.9483x over previous
#include <cuda_runtime.h>
#include <cuda_bf16.h>
#include <cstdint>

#define N_NODES 50000
#define N_EDGES 800000
#define F 128

// ---- device scratch (no allocs allowed) ----
__device__ float g_h[N_NODES * F];        // h = feat @ Wp^T + bp
__device__ float g_wsum[N_NODES];
__device__ int   g_cnt[N_NODES];
__device__ int   g_rowptr[N_NODES + 1];
__device__ int   g_cursor[N_NODES];
__device__ int   g_ssrc[N_EDGES];         // src sorted by dst
__device__ float g_sm[N_EDGES];           // m  sorted by dst
__device__ __nv_bfloat16 g_wh[2][F * F];  // [mat][n*F+k] hi split of W (0=Wp,1=Ws)
__device__ __nv_bfloat16 g_wl[2][F * F];  // lo split

#define SCAN_BLK 512
#define SCAN_NB  ((N_NODES + SCAN_BLK - 1) / SCAN_BLK)   // 98
__device__ int g_bsum[SCAN_NB];
__device__ int g_bofs[SCAN_NB];

// ======================= small kernels (CSR build) =======================
__global__ void k_init() {
    int i = blockIdx.x * blockDim.x + threadIdx.x;
    if (i < N_NODES) { g_wsum[i] = 0.f; g_cnt[i] = 0; }
}

__global__ void k_count(const float* __restrict__ efeat, const int* __restrict__ dst) {
    int e = blockIdx.x * blockDim.x + threadIdx.x;
    if (e < N_EDGES) {
        int d = dst[e];
        atomicAdd(&g_wsum[d], efeat[e]);
        atomicAdd(&g_cnt[d], 1);
    }
}

// ---- scan phase A: per-block sums of g_cnt ----
__global__ void k_bsum() {
    __shared__ int ws[16];
    int t = threadIdx.x, lane = t & 31, wid = t >> 5;
    int i = blockIdx.x * SCAN_BLK + t;
    int v = (i < N_NODES) ? g_cnt[i] : 0;
    #pragma unroll
    for (int off = 16; off > 0; off >>= 1) v += __shfl_xor_sync(0xffffffffu, v, off);
    if (lane == 0) ws[wid] = v;
    __syncthreads();
    if (t < 16) {
        int s = ws[t];
        #pragma unroll
        for (int off = 8; off > 0; off >>= 1) s += __shfl_xor_sync(0xffffu, s, off);
        if (t == 0) g_bsum[blockIdx.x] = s;
    }
}

// ---- scan phase B: exclusive scan of 98 block sums (1 small block) ----
__global__ void k_bscan() {
    __shared__ int wsum[4];
    int t = threadIdx.x, lane = t & 31, wid = t >> 5;   // 128 threads
    int x = (t < SCAN_NB) ? g_bsum[t] : 0;
    int v = x;
    #pragma unroll
    for (int off = 1; off < 32; off <<= 1) {
        int u = __shfl_up_sync(0xffffffffu, v, off);
        if (lane >= off) v += u;
    }
    if (lane == 31) wsum[wid] = v;
    __syncthreads();
    int add = 0;
    for (int k = 0; k < wid; ++k) add += wsum[k];
    int incl = v + add;
    if (t < SCAN_NB) g_bofs[t] = incl - x;
    if (t == SCAN_NB - 1) g_rowptr[N_NODES] = incl;
}

// ---- scan phase C: block-local exclusive scan + block offset ----
__global__ void k_applyscan() {
    __shared__ int ws[16];
    int t = threadIdx.x, lane = t & 31, wid = t >> 5;
    int i = blockIdx.x * SCAN_BLK + t;
    int x = (i < N_NODES) ? g_cnt[i] : 0;
    int v = x;
    #pragma unroll
    for (int off = 1; off < 32; off <<= 1) {
        int u = __shfl_up_sync(0xffffffffu, v, off);
        if (lane >= off) v += u;
    }
    if (lane == 31) ws[wid] = v;
    __syncthreads();
    if (t < 16) {
        int wv = ws[t];
        int vv = wv;
        #pragma unroll
        for (int off = 1; off < 16; off <<= 1) {
            int u = __shfl_up_sync(0xffffu, vv, off);
            if (t >= off) vv += u;
        }
        ws[t] = vv - wv;
    }
    __syncthreads();
    int excl = (v - x) + ws[wid] + g_bofs[blockIdx.x];
    if (i < N_NODES) { g_rowptr[i] = excl; g_cursor[i] = excl; }
}

__global__ void k_scatter(const float* __restrict__ efeat, const int* __restrict__ src,
                          const int* __restrict__ dst) {
    int e = blockIdx.x * blockDim.x + threadIdx.x;
    if (e < N_EDGES) {
        int d = dst[e];
        float w = efeat[e];
        float m = expf(-w / g_wsum[d]);
        int pos = atomicAdd(&g_cursor[d], 1);
        g_ssrc[pos] = src[e];
        g_sm[pos] = m;
    }
}

// ---- split W matrices into hi/lo bf16 (once) ----
__global__ void k_wsplit(const float* __restrict__ Wp, const float* __restrict__ Ws) {
    int i = blockIdx.x * blockDim.x + threadIdx.x;
    if (i < F * F) {
        float w = Wp[i];
        __nv_bfloat16 h = __float2bfloat16(w);
        g_wh[0][i] = h;
        g_wl[0][i] = __float2bfloat16(w - __bfloat162float(h));
        w = Ws[i];
        h = __float2bfloat16(w);
        g_wh[1][i] = h;
        g_wl[1][i] = __float2bfloat16(w - __bfloat162float(h));
    }
}

// ======================= HMMA dual GEMM (bf16x3 split) =======================
// M-tile = 64, 8 warps: row-group = w&3 (16 rows), col-half = w>>2 (64 cols).
// smem 104 KB -> 2 CTAs/SM (16 warps/SM).

#define STRIDE 136                         // bf16 elems per smem row (padded)
#define SM_A_HI 0
#define SM_A_LO (64 * STRIDE)
#define SM_W_HI (128 * STRIDE)
#define SM_W_LO (128 * STRIDE + 128 * STRIDE)
#define SM_GEMM_BYTES ((128 + 256) * STRIDE * 2)   // 104448

__device__ __forceinline__ uint32_t smem_u32(const void* p) {
    uint32_t a;
    asm("{ .reg .u64 t; cvta.to.shared.u64 t, %1; cvt.u32.u64 %0, t; }" : "=r"(a) : "l"(p));
    return a;
}
__device__ __forceinline__ void ldsm4(uint32_t& r0, uint32_t& r1, uint32_t& r2, uint32_t& r3,
                                      uint32_t addr) {
    asm volatile("ldmatrix.sync.aligned.m8n8.x4.shared.b16 {%0,%1,%2,%3},[%4];"
                 : "=r"(r0), "=r"(r1), "=r"(r2), "=r"(r3) : "r"(addr));
}
__device__ __forceinline__ void mma16816(float* d, const uint32_t* a, uint32_t b0, uint32_t b1) {
    asm volatile(
        "mma.sync.aligned.m16n8k16.row.col.f32.bf16.bf16.f32 "
        "{%0,%1,%2,%3},{%4,%5,%6,%7},{%8,%9},{%0,%1,%2,%3};"
        : "+f"(d[0]), "+f"(d[1]), "+f"(d[2]), "+f"(d[3])
        : "r"(a[0]), "r"(a[1]), "r"(a[2]), "r"(a[3]), "r"(b0), "r"(b1));
}
__device__ __forceinline__ unsigned pack2(__nv_bfloat16 a, __nv_bfloat16 b) {
    return (unsigned)__bfloat16_as_ushort(a) | ((unsigned)__bfloat16_as_ushort(b) << 16);
}

__global__ __launch_bounds__(256, 2)
void k_gemm_mma(const float* __restrict__ feat,
                const float* __restrict__ bp, const float* __restrict__ bs,
                float* __restrict__ out) {
    extern __shared__ __nv_bfloat16 sm[];
    int tid = threadIdx.x, w = tid >> 5, lane = tid & 31;
    int m0 = blockIdx.x * 64;
    int rows_valid = N_NODES - m0; if (rows_valid > 64) rows_valid = 64;

    // ---- convert A tile (64x128 f32 -> hi/lo bf16, padded smem) ----
    for (int i = tid; i < 2048; i += 256) {          // 2048 float4s
        int r = i >> 5, c4 = (i & 31) << 2;
        float4 v = make_float4(0.f, 0.f, 0.f, 0.f);
        if (r < rows_valid) v = *(const float4*)&feat[(long)(m0 + r) * F + c4];
        __nv_bfloat16 h0 = __float2bfloat16(v.x), h1 = __float2bfloat16(v.y);
        __nv_bfloat16 h2 = __float2bfloat16(v.z), h3 = __float2bfloat16(v.w);
        __nv_bfloat16 l0 = __float2bfloat16(v.x - __bfloat162float(h0));
        __nv_bfloat16 l1 = __float2bfloat16(v.y - __bfloat162float(h1));
        __nv_bfloat16 l2 = __float2bfloat16(v.z - __bfloat162float(h2));
        __nv_bfloat16 l3 = __float2bfloat16(v.w - __bfloat162float(h3));
        int o = r * STRIDE + c4;
        *(uint2*)&sm[SM_A_HI + o] = make_uint2(pack2(h0, h1), pack2(h2, h3));
        *(uint2*)&sm[SM_A_LO + o] = make_uint2(pack2(l0, l1), pack2(l2, l3));
    }

    uint32_t sb = smem_u32(sm);
    uint32_t aRow = (uint32_t)((w & 3) * 16 + (lane & 15));
    uint32_t aColB = (uint32_t)((lane >> 4) << 4);
    uint32_t aHiAddr = sb + SM_A_HI * 2 + aRow * (STRIDE * 2) + aColB;
    uint32_t aLoAddr = sb + SM_A_LO * 2 + aRow * (STRIDE * 2) + aColB;
    uint32_t bRowIn16 = (uint32_t)((lane & 7) + ((lane >> 4) << 3));
    uint32_t bColB = (uint32_t)(((lane >> 3) & 1) << 4);
    uint32_t nHalf = (uint32_t)((w >> 2) * 64);
    uint32_t bHiBase = sb + SM_W_HI * 2 + (nHalf + bRowIn16) * (STRIDE * 2) + bColB;
    uint32_t bLoBase = sb + SM_W_LO * 2 + (nHalf + bRowIn16) * (STRIDE * 2) + bColB;

    #pragma unroll
    for (int mat = 0; mat < 2; ++mat) {
        __syncthreads();     // mat1: wait until all warps done reading previous W
        for (int i = tid; i < 4096; i += 256) {
            int r = i >> 5, c4 = (i & 31) << 2;
            int o = r * STRIDE + c4;
            *(uint2*)&sm[SM_W_HI + o] = *(const uint2*)&g_wh[mat][r * F + c4];
            *(uint2*)&sm[SM_W_LO + o] = *(const uint2*)&g_wl[mat][r * F + c4];
        }
        __syncthreads();

        float d[8][4];
        #pragma unroll
        for (int nt = 0; nt < 8; ++nt)
            #pragma unroll
            for (int j = 0; j < 4; ++j) d[nt][j] = 0.f;

        #pragma unroll
        for (int k = 0; k < 8; ++k) {
            uint32_t kOffB = (uint32_t)(k * 32);    // 16 elems = 32B
            uint32_t ahi[4], alo[4];
            ldsm4(ahi[0], ahi[1], ahi[2], ahi[3], aHiAddr + kOffB);
            ldsm4(alo[0], alo[1], alo[2], alo[3], aLoAddr + kOffB);
            #pragma unroll
            for (int bt = 0; bt < 4; ++bt) {        // 16 n-rows per iteration
                uint32_t nOffB = (uint32_t)(bt * 16 * STRIDE * 2);
                uint32_t bh[4], bl[4];
                ldsm4(bh[0], bh[1], bh[2], bh[3], bHiBase + nOffB + kOffB);
                ldsm4(bl[0], bl[1], bl[2], bl[3], bLoBase + nOffB + kOffB);
                mma16816(d[bt * 2],     ahi, bh[0], bh[1]);
                mma16816(d[bt * 2 + 1], ahi, bh[2], bh[3]);
                mma16816(d[bt * 2],     ahi, bl[0], bl[1]);
                mma16816(d[bt * 2 + 1], ahi, bl[2], bl[3]);
                mma16816(d[bt * 2],     alo, bh[0], bh[1]);
                mma16816(d[bt * 2 + 1], alo, bh[2], bh[3]);
            }
        }

        // ---- epilogue: registers -> gmem with bias ----
        const float* bias = mat ? bs : bp;
        float* dstp = mat ? out : g_h;
        int r0 = m0 + (w & 3) * 16 + (lane >> 2);
        #pragma unroll
        for (int nt = 0; nt < 8; ++nt) {
            int c = (int)nHalf + nt * 8 + (lane & 3) * 2;
            float b0 = __ldg(&bias[c]), b1 = __ldg(&bias[c + 1]);
            if (r0 < N_NODES) {
                float2 v = make_float2(d[nt][0] + b0, d[nt][1] + b1);
                *(float2*)&dstp[(long)r0 * F + c] = v;
            }
            if (r0 + 8 < N_NODES) {
                float2 v = make_float2(d[nt][2] + b0, d[nt][3] + b1);
                *(float2*)&dstp[(long)(r0 + 8) * F + c] = v;
            }
        }
    }
}

// ======================= warp-per-node CSR aggregation =======================
__global__ void k_agg(float* __restrict__ out) {
    int node = (blockIdx.x * blockDim.x + threadIdx.x) >> 5;
    int lane = threadIdx.x & 31;
    if (node >= N_NODES) return;
    int beg = g_rowptr[node], end = g_rowptr[node + 1];

    float4 acc = make_float4(0.f, 0.f, 0.f, 0.f);
    for (int e0 = beg; e0 < end; e0 += 32) {
        int i = e0 + lane;
        int s = 0; float mv = 0.f;
        if (i < end) { s = g_ssrc[i]; mv = g_sm[i]; }
        int cnt = min(32, end - e0);
        for (int j = 0; j < cnt; ++j) {
            int ss = __shfl_sync(0xffffffffu, s, j);
            float mm = __shfl_sync(0xffffffffu, mv, j);
            float4 hv = *(const float4*)&g_h[(long)ss * F + lane * 4];
            acc.x += mm * hv.x;
            acc.y += mm * hv.y;
            acc.z += mm * hv.z;
            acc.w += mm * hv.w;
        }
    }
    int deg = end - beg;
    float inv = 1.0f / (float)(deg > 1 ? deg : 1);
    float4* po = (float4*)&out[(long)node * F + lane * 4];
    float4 o = *po;
    o.x += acc.x * inv;
    o.y += acc.y * inv;
    o.z += acc.z * inv;
    o.w += acc.w * inv;
    *po = o;
}

extern "C" void kernel_launch(void* const* d_in, const int* in_sizes, int n_in,
                              void* d_out, int out_size) {
    const float* feat  = (const float*)d_in[0];
    const float* efeat = (const float*)d_in[1];
    const int*   src   = (const int*)d_in[2];
    const int*   dst   = (const int*)d_in[3];
    const float* Wp    = (const float*)d_in[4];
    const float* bp    = (const float*)d_in[5];
    const float* Ws    = (const float*)d_in[6];
    const float* bs    = (const float*)d_in[7];
    float* out = (float*)d_out;

    cudaFuncSetAttribute(k_gemm_mma, cudaFuncAttributeMaxDynamicSharedMemorySize, SM_GEMM_BYTES);

    k_wsplit<<<(F * F + 255) / 256, 256>>>(Wp, Ws);
    k_init<<<(N_NODES + 255) / 256, 256>>>();
    k_count<<<(N_EDGES + 255) / 256, 256>>>(efeat, dst);
    k_bsum<<<SCAN_NB, SCAN_BLK>>>();
    k_bscan<<<1, 128>>>();
    k_applyscan<<<SCAN_NB, SCAN_BLK>>>();
    k_scatter<<<(N_EDGES + 255) / 256, 256>>>(efeat, src, dst);
    k_gemm_mma<<<(N_NODES + 63) / 64, 256, SM_GEMM_BYTES>>>(feat, bp, bs, out);
    k_agg<<<(N_NODES * 32 + 255) / 256, 256>>>(out);
}

// round 6
// speedup vs baseline: 2.2857x; 1.1732x over previous
#include <cuda_runtime.h>
#include <cuda_bf16.h>
#include <cstdint>

#define N_NODES 50000
#define N_EDGES 800000
#define F 128

// ---- device scratch (no allocs allowed) ----
__device__ float g_aggf[N_NODES * F];     // (sum_e m_e feat[src_e]) / max(deg,1)
__device__ float g_msum[N_NODES];         // (sum_e m_e) / max(deg,1)
__device__ int   g_cnt[N_NODES];
__device__ int   g_rowptr[N_NODES + 1];
__device__ int   g_cursor[N_NODES];
__device__ uint2 g_edge[N_EDGES];         // (src, w_bits) sorted by dst
__device__ __nv_bfloat16 g_wh[2][F * F];  // [mat][n*F+k] hi split (0=Wp,1=Ws)
__device__ __nv_bfloat16 g_wl[2][F * F];  // lo split

#define SCAN_BLK 512
#define SCAN_NB  ((N_NODES + SCAN_BLK - 1) / SCAN_BLK)   // 98
__device__ int g_bsum[SCAN_NB];
__device__ int g_bofs[SCAN_NB];

// ======================= setup: W split + cnt zero (fused) =======================
__global__ void k_setup(const float* __restrict__ Wp, const float* __restrict__ Ws) {
    int i = blockIdx.x * blockDim.x + threadIdx.x;
    if (i < F * F) {
        float w = Wp[i];
        __nv_bfloat16 h = __float2bfloat16(w);
        g_wh[0][i] = h;
        g_wl[0][i] = __float2bfloat16(w - __bfloat162float(h));
        w = Ws[i];
        h = __float2bfloat16(w);
        g_wh[1][i] = h;
        g_wl[1][i] = __float2bfloat16(w - __bfloat162float(h));
    }
    if (i < N_NODES) g_cnt[i] = 0;
}

// ======================= CSR build =======================
__global__ void k_count(const int* __restrict__ dst) {
    int e = blockIdx.x * blockDim.x + threadIdx.x;
    if (e < N_EDGES) atomicAdd(&g_cnt[dst[e]], 1);
}

__global__ void k_bsum() {
    __shared__ int ws[16];
    int t = threadIdx.x, lane = t & 31, wid = t >> 5;
    int i = blockIdx.x * SCAN_BLK + t;
    int v = (i < N_NODES) ? g_cnt[i] : 0;
    #pragma unroll
    for (int off = 16; off > 0; off >>= 1) v += __shfl_xor_sync(0xffffffffu, v, off);
    if (lane == 0) ws[wid] = v;
    __syncthreads();
    if (t < 16) {
        int s = ws[t];
        #pragma unroll
        for (int off = 8; off > 0; off >>= 1) s += __shfl_xor_sync(0xffffu, s, off);
        if (t == 0) g_bsum[blockIdx.x] = s;
    }
}

__global__ void k_bscan() {
    __shared__ int wsum[4];
    int t = threadIdx.x, lane = t & 31, wid = t >> 5;   // 128 threads
    int x = (t < SCAN_NB) ? g_bsum[t] : 0;
    int v = x;
    #pragma unroll
    for (int off = 1; off < 32; off <<= 1) {
        int u = __shfl_up_sync(0xffffffffu, v, off);
        if (lane >= off) v += u;
    }
    if (lane == 31) wsum[wid] = v;
    __syncthreads();
    int add = 0;
    for (int k = 0; k < wid; ++k) add += wsum[k];
    int incl = v + add;
    if (t < SCAN_NB) g_bofs[t] = incl - x;
    if (t == SCAN_NB - 1) g_rowptr[N_NODES] = incl;
}

__global__ void k_applyscan() {
    __shared__ int ws[16];
    int t = threadIdx.x, lane = t & 31, wid = t >> 5;
    int i = blockIdx.x * SCAN_BLK + t;
    int x = (i < N_NODES) ? g_cnt[i] : 0;
    int v = x;
    #pragma unroll
    for (int off = 1; off < 32; off <<= 1) {
        int u = __shfl_up_sync(0xffffffffu, v, off);
        if (lane >= off) v += u;
    }
    if (lane == 31) ws[wid] = v;
    __syncthreads();
    if (t < 16) {
        int wv = ws[t];
        int vv = wv;
        #pragma unroll
        for (int off = 1; off < 16; off <<= 1) {
            int u = __shfl_up_sync(0xffffu, vv, off);
            if (t >= off) vv += u;
        }
        ws[t] = vv - wv;
    }
    __syncthreads();
    int excl = (v - x) + ws[wid] + g_bofs[blockIdx.x];
    if (i < N_NODES) { g_rowptr[i] = excl; g_cursor[i] = excl; }
}

__global__ void k_scatter(const float* __restrict__ efeat, const int* __restrict__ src,
                          const int* __restrict__ dst) {
    int e = blockIdx.x * blockDim.x + threadIdx.x;
    if (e < N_EDGES) {
        int d = dst[e];
        int pos = atomicAdd(&g_cursor[d], 1);
        g_edge[pos] = make_uint2((unsigned)src[e], __float_as_uint(efeat[e]));
    }
}

// ======================= warp-per-node feature aggregation =======================
// aggf[n] = (sum_e m_e * feat[src_e]) / max(deg,1),  msum[n] = (sum_e m_e)/max(deg,1)
// with m_e = exp(-w_e / wsum_n), wsum_n computed from the node's CSR list.
__global__ void k_agg(const float* __restrict__ feat) {
    int node = (blockIdx.x * blockDim.x + threadIdx.x) >> 5;
    int lane = threadIdx.x & 31;
    if (node >= N_NODES) return;
    int beg = g_rowptr[node], end = g_rowptr[node + 1];
    int deg = end - beg;

    // pass 1: wsum over this node's edges
    float wsum = 0.f;
    for (int i = beg + lane; i < end; i += 32)
        wsum += __uint_as_float(g_edge[i].y);
    #pragma unroll
    for (int off = 16; off > 0; off >>= 1)
        wsum += __shfl_xor_sync(0xffffffffu, wsum, off);

    float inv_w = (deg > 0) ? (1.0f / wsum) : 0.f;

    // pass 2: gather + weighted sum
    float4 acc = make_float4(0.f, 0.f, 0.f, 0.f);
    float msum = 0.f;
    for (int e0 = beg; e0 < end; e0 += 32) {
        int i = e0 + lane;
        unsigned s = 0; float m = 0.f;
        if (i < end) {
            uint2 ed = g_edge[i];
            s = ed.x;
            m = __expf(-__uint_as_float(ed.y) * inv_w);
        }
        int cnt = min(32, end - e0);
        for (int j = 0; j < cnt; ++j) {
            unsigned ss = __shfl_sync(0xffffffffu, s, j);
            float mm = __shfl_sync(0xffffffffu, m, j);
            float4 hv = *(const float4*)&feat[(long)ss * F + lane * 4];
            acc.x += mm * hv.x;
            acc.y += mm * hv.y;
            acc.z += mm * hv.z;
            acc.w += mm * hv.w;
            msum += mm;
        }
    }
    float inv = 1.0f / (float)(deg > 1 ? deg : 1);
    acc.x *= inv; acc.y *= inv; acc.z *= inv; acc.w *= inv;
    *(float4*)&g_aggf[(long)node * F + lane * 4] = acc;
    if (lane == 0) g_msum[node] = msum * inv;
}

// ======================= HMMA fused dual GEMM (bf16x3 split) =======================
// out = feat@Ws^T + aggf@Wp^T + bs + msum*bp
// phase 0: A=aggf, W=Wp ; phase 1: A=feat, W=Ws ; accumulate in registers.

#define STRIDE 136
#define SM_A_HI 0
#define SM_A_LO (64 * STRIDE)
#define SM_W_HI (128 * STRIDE)
#define SM_W_LO (256 * STRIDE)
#define SM_GEMM_BYTES (384 * STRIDE * 2)   // 104448

__device__ __forceinline__ uint32_t smem_u32(const void* p) {
    uint32_t a;
    asm("{ .reg .u64 t; cvta.to.shared.u64 t, %1; cvt.u32.u64 %0, t; }" : "=r"(a) : "l"(p));
    return a;
}
__device__ __forceinline__ void ldsm4(uint32_t& r0, uint32_t& r1, uint32_t& r2, uint32_t& r3,
                                      uint32_t addr) {
    asm volatile("ldmatrix.sync.aligned.m8n8.x4.shared.b16 {%0,%1,%2,%3},[%4];"
                 : "=r"(r0), "=r"(r1), "=r"(r2), "=r"(r3) : "r"(addr));
}
__device__ __forceinline__ void mma16816(float* d, const uint32_t* a, uint32_t b0, uint32_t b1) {
    asm volatile(
        "mma.sync.aligned.m16n8k16.row.col.f32.bf16.bf16.f32 "
        "{%0,%1,%2,%3},{%4,%5,%6,%7},{%8,%9},{%0,%1,%2,%3};"
        : "+f"(d[0]), "+f"(d[1]), "+f"(d[2]), "+f"(d[3])
        : "r"(a[0]), "r"(a[1]), "r"(a[2]), "r"(a[3]), "r"(b0), "r"(b1));
}
__device__ __forceinline__ unsigned pack2(__nv_bfloat16 a, __nv_bfloat16 b) {
    return (unsigned)__bfloat16_as_ushort(a) | ((unsigned)__bfloat16_as_ushort(b) << 16);
}

__global__ __launch_bounds__(256, 2)
void k_gemm_mma(const float* __restrict__ feat,
                const float* __restrict__ bp, const float* __restrict__ bs,
                float* __restrict__ out) {
    extern __shared__ __nv_bfloat16 sm[];
    int tid = threadIdx.x, w = tid >> 5, lane = tid & 31;
    int m0 = blockIdx.x * 64;
    int rows_valid = N_NODES - m0; if (rows_valid > 64) rows_valid = 64;

    uint32_t sb = smem_u32(sm);
    uint32_t aRow = (uint32_t)((w & 3) * 16 + (lane & 15));
    uint32_t aColB = (uint32_t)((lane >> 4) << 4);
    uint32_t aHiAddr = sb + SM_A_HI * 2 + aRow * (STRIDE * 2) + aColB;
    uint32_t aLoAddr = sb + SM_A_LO * 2 + aRow * (STRIDE * 2) + aColB;
    uint32_t bRowIn16 = (uint32_t)((lane & 7) + ((lane >> 4) << 3));
    uint32_t bColB = (uint32_t)(((lane >> 3) & 1) << 4);
    uint32_t nHalf = (uint32_t)((w >> 2) * 64);
    uint32_t bHiBase = sb + SM_W_HI * 2 + (nHalf + bRowIn16) * (STRIDE * 2) + bColB;
    uint32_t bLoBase = sb + SM_W_LO * 2 + (nHalf + bRowIn16) * (STRIDE * 2) + bColB;

    float d[8][4];
    #pragma unroll
    for (int nt = 0; nt < 8; ++nt)
        #pragma unroll
        for (int j = 0; j < 4; ++j) d[nt][j] = 0.f;

    #pragma unroll
    for (int phase = 0; phase < 2; ++phase) {
        const float* Ap = phase ? (feat + (long)m0 * F) : (g_aggf + (long)m0 * F);
        __syncthreads();   // phase1: all warps done reading previous tiles

        // convert A tile (64x128 f32 -> hi/lo bf16)
        for (int i = tid; i < 2048; i += 256) {
            int r = i >> 5, c4 = (i & 31) << 2;
            float4 v = make_float4(0.f, 0.f, 0.f, 0.f);
            if (r < rows_valid) v = *(const float4*)&Ap[(long)r * F + c4];
            __nv_bfloat16 h0 = __float2bfloat16(v.x), h1 = __float2bfloat16(v.y);
            __nv_bfloat16 h2 = __float2bfloat16(v.z), h3 = __float2bfloat16(v.w);
            __nv_bfloat16 l0 = __float2bfloat16(v.x - __bfloat162float(h0));
            __nv_bfloat16 l1 = __float2bfloat16(v.y - __bfloat162float(h1));
            __nv_bfloat16 l2 = __float2bfloat16(v.z - __bfloat162float(h2));
            __nv_bfloat16 l3 = __float2bfloat16(v.w - __bfloat162float(h3));
            int o = r * STRIDE + c4;
            *(uint2*)&sm[SM_A_HI + o] = make_uint2(pack2(h0, h1), pack2(h2, h3));
            *(uint2*)&sm[SM_A_LO + o] = make_uint2(pack2(l0, l1), pack2(l2, l3));
        }
        // load pre-split W tile (phase 0 -> Wp, phase 1 -> Ws)
        for (int i = tid; i < 4096; i += 256) {
            int r = i >> 5, c4 = (i & 31) << 2;
            int o = r * STRIDE + c4;
            *(uint2*)&sm[SM_W_HI + o] = *(const uint2*)&g_wh[phase][r * F + c4];
            *(uint2*)&sm[SM_W_LO + o] = *(const uint2*)&g_wl[phase][r * F + c4];
        }
        __syncthreads();

        #pragma unroll
        for (int k = 0; k < 8; ++k) {
            uint32_t kOffB = (uint32_t)(k * 32);
            uint32_t ahi[4], alo[4];
            ldsm4(ahi[0], ahi[1], ahi[2], ahi[3], aHiAddr + kOffB);
            ldsm4(alo[0], alo[1], alo[2], alo[3], aLoAddr + kOffB);
            #pragma unroll
            for (int bt = 0; bt < 4; ++bt) {
                uint32_t nOffB = (uint32_t)(bt * 16 * STRIDE * 2);
                uint32_t bh[4], bl[4];
                ldsm4(bh[0], bh[1], bh[2], bh[3], bHiBase + nOffB + kOffB);
                ldsm4(bl[0], bl[1], bl[2], bl[3], bLoBase + nOffB + kOffB);
                mma16816(d[bt * 2],     ahi, bh[0], bh[1]);
                mma16816(d[bt * 2 + 1], ahi, bh[2], bh[3]);
                mma16816(d[bt * 2],     ahi, bl[0], bl[1]);
                mma16816(d[bt * 2 + 1], ahi, bl[2], bl[3]);
                mma16816(d[bt * 2],     alo, bh[0], bh[1]);
                mma16816(d[bt * 2 + 1], alo, bh[2], bh[3]);
            }
        }
    }

    // ---- epilogue: out = d + bs + msum*bp ----
    int r0 = m0 + (w & 3) * 16 + (lane >> 2);
    float ms0 = (r0 < N_NODES)     ? g_msum[r0]     : 0.f;
    float ms1 = (r0 + 8 < N_NODES) ? g_msum[r0 + 8] : 0.f;
    #pragma unroll
    for (int nt = 0; nt < 8; ++nt) {
        int c = (int)nHalf + nt * 8 + (lane & 3) * 2;
        float p0 = __ldg(&bp[c]), p1 = __ldg(&bp[c + 1]);
        float s0 = __ldg(&bs[c]), s1 = __ldg(&bs[c + 1]);
        if (r0 < N_NODES) {
            float2 v = make_float2(d[nt][0] + s0 + ms0 * p0,
                                   d[nt][1] + s1 + ms0 * p1);
            *(float2*)&out[(long)r0 * F + c] = v;
        }
        if (r0 + 8 < N_NODES) {
            float2 v = make_float2(d[nt][2] + s0 + ms1 * p0,
                                   d[nt][3] + s1 + ms1 * p1);
            *(float2*)&out[(long)(r0 + 8) * F + c] = v;
        }
    }
}

extern "C" void kernel_launch(void* const* d_in, const int* in_sizes, int n_in,
                              void* d_out, int out_size) {
    const float* feat  = (const float*)d_in[0];
    const float* efeat = (const float*)d_in[1];
    const int*   src   = (const int*)d_in[2];
    const int*   dst   = (const int*)d_in[3];
    const float* Wp    = (const float*)d_in[4];
    const float* bp    = (const float*)d_in[5];
    const float* Ws    = (const float*)d_in[6];
    const float* bs    = (const float*)d_in[7];
    float* out = (float*)d_out;

    cudaFuncSetAttribute(k_gemm_mma, cudaFuncAttributeMaxDynamicSharedMemorySize, SM_GEMM_BYTES);

    k_setup<<<(N_NODES + 255) / 256, 256>>>(Wp, Ws);
    k_count<<<(N_EDGES + 255) / 256, 256>>>(dst);
    k_bsum<<<SCAN_NB, SCAN_BLK>>>();
    k_bscan<<<1, 128>>>();
    k_applyscan<<<SCAN_NB, SCAN_BLK>>>();
    k_scatter<<<(N_EDGES + 255) / 256, 256>>>(efeat, src, dst);
    k_agg<<<(N_NODES * 32 + 255) / 256, 256>>>(feat);
    k_gemm_mma<<<(N_NODES + 63) / 64, 256, SM_GEMM_BYTES>>>(feat, bp, bs, out);
}